// round 6
// baseline (speedup 1.0000x reference)
#include <cuda_runtime.h>

#define N_NODES 50000
#define E_EDGES 800000
#define F_INN   512
#define HIDD    128

// ---------------- scratch (no allocs allowed) ----------------
__device__ float g_u1[F_INN];       // gcn_w @ w1
__device__ float g_u2[F_INN];       // gcn_w @ w2
__device__ float g_beta;            // gcn_b.(w1+w2) + mlp_b
__device__ float g_p1[N_NODES];     // feat[n].u1
__device__ float g_p2[N_NODES];     // feat[n].u2
__device__ float g_a[N_NODES];      // segment scatter of v*p1[col]
__device__ float g_c[N_NODES];      // segment scatter of v*p2[col]
__device__ float g_s[N_NODES];      // per-row sum of exp
__device__ float g_t[E_EDGES];      // per-edge exp (L2-resident)
__device__ int2  g_rc[E_EDGES];     // packed (row, col)

#define EPT 4   // edges per thread in edge kernels

// Per-block index-dtype detection: reads 16 leading int64 words (L2-cached,
// identical across blocks). int64 indices are all in [0, N); int32 data
// reinterpreted as int64 is out of range almost surely.
__device__ __forceinline__ int detect_is64(const void* idx) {
    const long long* p = (const long long*)idx;
    int is64 = 1;
#pragma unroll
    for (int i = 0; i < 16; i++) {
        long long v = p[i];
        if (v < 0 || v >= N_NODES) { is64 = 0; break; }
    }
    return is64;
}

// ---------------- K1: setup — u1/u2, beta, zero a/c/s ----------------
__global__ __launch_bounds__(256) void setup_kernel(const float* __restrict__ gcn_w,
                                                    const float* __restrict__ gcn_b,
                                                    const float* __restrict__ mlp_w,
                                                    const float* __restrict__ mlp_b) {
    int b = blockIdx.x;
    if (b < 2) {
        int k = b * 256 + threadIdx.x;           // 0..511
        const float* wrow = gcn_w + (size_t)k * HIDD;
        float s1 = 0.f, s2 = 0.f;
#pragma unroll 8
        for (int j = 0; j < HIDD; j++) {
            float w = wrow[j];
            s1 += w * mlp_w[j];
            s2 += w * mlp_w[HIDD + j];
        }
        g_u1[k] = s1;
        g_u2[k] = s2;
    } else if (b == 2) {
        if (threadIdx.x < 32) {
            int lane = threadIdx.x;
            float s = 0.f;
            for (int j = lane; j < HIDD; j += 32)
                s += gcn_b[j] * (mlp_w[j] + mlp_w[HIDD + j]);
#pragma unroll
            for (int o = 16; o > 0; o >>= 1) s += __shfl_xor_sync(0xFFFFFFFFu, s, o);
            if (lane == 0) g_beta = s + mlp_b[0];
        }
    } else {
        int i = (b - 3) * 256 + threadIdx.x;
        if (i < N_NODES) { g_a[i] = 0.f; g_c[i] = 0.f; g_s[i] = 0.f; }
    }
}

// ---------------- K2: p1[n]=feat[n].u1, p2[n]=feat[n].u2 (warp/node) ----------------
__global__ __launch_bounds__(256) void p_kernel(const float* __restrict__ feat) {
    __shared__ float su1[F_INN];
    __shared__ float su2[F_INN];
    for (int i = threadIdx.x; i < F_INN; i += 256) {
        su1[i] = g_u1[i];
        su2[i] = g_u2[i];
    }
    __syncthreads();

    int n = blockIdx.x * 8 + (threadIdx.x >> 5);
    if (n >= N_NODES) return;
    int lane = threadIdx.x & 31;
    const float* frow = feat + (size_t)n * F_INN;
    float s1 = 0.f, s2 = 0.f;
#pragma unroll
    for (int ch = 0; ch < 4; ch++) {
        int o = ch * 128 + lane * 4;
        float4 f = *(const float4*)(frow + o);
        s1 += f.x * su1[o] + f.y * su1[o + 1] + f.z * su1[o + 2] + f.w * su1[o + 3];
        s2 += f.x * su2[o] + f.y * su2[o + 1] + f.z * su2[o + 2] + f.w * su2[o + 3];
    }
#pragma unroll
    for (int o = 16; o > 0; o >>= 1) {
        s1 += __shfl_xor_sync(0xFFFFFFFFu, s1, o);
        s2 += __shfl_xor_sync(0xFFFFFFFFu, s2, o);
    }
    if (lane == 0) { g_p1[n] = s1; g_p2[n] = s2; }
}

// ---------------- K3: convert indices, pack rc, scatter a/c ----------------
__global__ __launch_bounds__(256) void scatter_kernel(const void* __restrict__ idx,
                                                      const float* __restrict__ vals) {
    int e0 = (blockIdx.x * 256 + threadIdx.x) * EPT;
    if (e0 >= E_EDGES) return;
    int r[EPT], c[EPT];
    if (detect_is64(idx)) {
        const long long* p = (const long long*)idx;
#pragma unroll
        for (int i = 0; i < EPT; i++) {
            r[i] = (int)p[e0 + i];
            c[i] = (int)p[E_EDGES + e0 + i];
        }
    } else {
        const int* p = (const int*)idx;
#pragma unroll
        for (int i = 0; i < EPT; i++) {
            r[i] = p[e0 + i];
            c[i] = p[E_EDGES + e0 + i];
        }
    }
    float v[EPT], p1[EPT], p2[EPT];
#pragma unroll
    for (int i = 0; i < EPT; i++) v[i] = vals[e0 + i];
#pragma unroll
    for (int i = 0; i < EPT; i++) { p1[i] = g_p1[c[i]]; p2[i] = g_p2[c[i]]; }
#pragma unroll
    for (int i = 0; i < EPT; i++) g_rc[e0 + i] = make_int2(r[i], c[i]);
#pragma unroll
    for (int i = 0; i < EPT; i++) {
        atomicAdd(&g_a[r[i]], v[i] * p1[i]);
        atomicAdd(&g_c[r[i]], v[i] * p2[i]);
    }
}

// ---------------- K4: ex = exp(a[r]+c[c]+beta); t[e]=ex; s[r]+=ex ----------------
__global__ __launch_bounds__(256) void sumexp_kernel() {
    int e0 = (blockIdx.x * 256 + threadIdx.x) * EPT;
    if (e0 >= E_EDGES) return;
    int2 rc[EPT];
#pragma unroll
    for (int i = 0; i < EPT; i++) rc[i] = g_rc[e0 + i];
    float av[EPT], cv[EPT];
#pragma unroll
    for (int i = 0; i < EPT; i++) { av[i] = g_a[rc[i].x]; cv[i] = g_c[rc[i].y]; }
    float beta = g_beta;
    float ex[EPT];
#pragma unroll
    for (int i = 0; i < EPT; i++) ex[i] = expf(av[i] + cv[i] + beta);
#pragma unroll
    for (int i = 0; i < EPT; i++) g_t[e0 + i] = ex[i];
#pragma unroll
    for (int i = 0; i < EPT; i++) atomicAdd(&g_s[rc[i].x], ex[i]);
}

// ---------------- K5: out = v + t[e]/s[row] ----------------
__global__ __launch_bounds__(256) void out_kernel(const float* __restrict__ vals,
                                                  float* __restrict__ out) {
    int e0 = (blockIdx.x * 256 + threadIdx.x) * EPT;
    if (e0 >= E_EDGES) return;
    int rr[EPT];
#pragma unroll
    for (int i = 0; i < EPT; i++) rr[i] = g_rc[e0 + i].x;
    float t[EPT], v[EPT], s[EPT];
#pragma unroll
    for (int i = 0; i < EPT; i++) t[i] = g_t[e0 + i];
#pragma unroll
    for (int i = 0; i < EPT; i++) v[i] = vals[e0 + i];
#pragma unroll
    for (int i = 0; i < EPT; i++) s[i] = g_s[rr[i]];
#pragma unroll
    for (int i = 0; i < EPT; i++) out[e0 + i] = v[i] + t[i] / s[i];
}

// ---------------- launch ----------------
extern "C" void kernel_launch(void* const* d_in, const int* in_sizes, int n_in,
                              void* d_out, int out_size) {
    const float* v_vals = (const float*)d_in[0];
    const float* feat   = (const float*)d_in[1];
    const void*  idx    = d_in[2];
    const float* gcn_w  = (const float*)d_in[n_in - 4];   // 512*128
    const float* gcn_b  = (const float*)d_in[n_in - 3];   // 128
    const float* mlp_w  = (const float*)d_in[n_in - 2];   // 256
    const float* mlp_b  = (const float*)d_in[n_in - 1];   // 1
    float*       out    = (float*)d_out;

    int init_blocks = 3 + (N_NODES + 255) / 256;
    setup_kernel<<<init_blocks, 256>>>(gcn_w, gcn_b, mlp_w, mlp_b);

    p_kernel<<<(N_NODES + 7) / 8, 256>>>(feat);

    int edge_blocks = (E_EDGES + 256 * EPT - 1) / (256 * EPT);
    scatter_kernel<<<edge_blocks, 256>>>(idx, v_vals);
    sumexp_kernel<<<edge_blocks, 256>>>();
    out_kernel<<<edge_blocks, 256>>>(v_vals, out);
}